// round 5
// baseline (speedup 1.0000x reference)
#include <cuda_runtime.h>

// Depthwise 1D conv: B=8, F=64, L=131072, K=9, pad=4 (SAME).
// x:      (B, F, L) float32, row (b,f) at (b*F + f)*L
// kernel: (F, 1, 9) float32
// out:    (F, B, 1, L) float32, row (f,b) at (f*B + b)*L
//
// One thread -> 16 contiguous outputs. Inputs: x[p-4 .. p+19] = 6 aligned
// float4 loads (zero-filled at row boundaries). 1.5x L1 read amplification
// (vs 3x for 4-output threads), MLP=6 independent LDG.128 per thread.

#define Lc 131072
#define Fc 64
#define Bc 8
#define EPT 16
#define CHUNKS_PER_ROW (Lc / EPT)         // 8192 = 2^13

__global__ __launch_bounds__(256) void dwconv1d_kernel(
    const float* __restrict__ x,
    const float* __restrict__ w,
    float* __restrict__ out)
{
    int t = blockIdx.x * blockDim.x + threadIdx.x;
    int q   = t & (CHUNKS_PER_ROW - 1);   // chunk index within row
    int row = t >> 13;                    // b*F + f
    int f = row & (Fc - 1);
    int b = row >> 6;
    int p = q << 4;                       // element offset within row

    const float* xr = x + (size_t)row * Lc;

    // 9 warp-uniform weight loads (all threads in a block share f:
    // 32 blocks per row, block never straddles a row)
    const float* wf = w + f * 9;
    float k[9];
#pragma unroll
    for (int i = 0; i < 9; i++) k[i] = wf[i];

    // a[i] = x[p - 4 + i], i = 0..23
    float a[24];

    float4 v;
    // prev quad (zero at row start)
    if (p >= 4) {
        v = *reinterpret_cast<const float4*>(xr + p - 4);
    } else {
        v = make_float4(0.f, 0.f, 0.f, 0.f);
    }
    a[0] = v.x; a[1] = v.y; a[2] = v.z; a[3] = v.w;

#pragma unroll
    for (int i = 0; i < 4; i++) {
        v = *reinterpret_cast<const float4*>(xr + p + i * 4);
        a[4 + i * 4 + 0] = v.x; a[4 + i * 4 + 1] = v.y;
        a[4 + i * 4 + 2] = v.z; a[4 + i * 4 + 3] = v.w;
    }

    // next quad past the chunk (zero at row end)
    if (p + EPT < Lc) {
        v = *reinterpret_cast<const float4*>(xr + p + 16);
    } else {
        v = make_float4(0.f, 0.f, 0.f, 0.f);
    }
    a[20] = v.x; a[21] = v.y; a[22] = v.z; a[23] = v.w;

    float* orow = out + ((size_t)(f * Bc + b)) * Lc + p;

#pragma unroll
    for (int g = 0; g < 4; g++) {
        float4 o;
        float* oj = &o.x;
#pragma unroll
        for (int j = 0; j < 4; j++) {
            int base = g * 4 + j;         // output index within chunk
            float s = a[base] * k[0];
#pragma unroll
            for (int kk = 1; kk < 9; kk++)
                s += a[base + kk] * k[kk];
            oj[j] = s;
        }
        *reinterpret_cast<float4*>(orow + g * 4) = o;
    }
}

extern "C" void kernel_launch(void* const* d_in, const int* in_sizes, int n_in,
                              void* d_out, int out_size)
{
    const float* x = (const float*)d_in[0];
    const float* w = (const float*)d_in[1];
    float* out = (float*)d_out;

    // total chunks = B*F*L/16 = 4,194,304 ; 256 threads/block -> 16384 blocks
    dim3 grid((Bc * Fc * CHUNKS_PER_ROW) / 256);
    dwconv1d_kernel<<<grid, 256>>>(x, w, out);
}

// round 6
// speedup vs baseline: 1.1603x; 1.1603x over previous
#include <cuda_runtime.h>

// Depthwise 1D conv: B=8, F=64, L=131072, K=9, pad=4 (SAME).
// x:      (B, F, L) float32, row (b,f) at (b*F + f)*L
// kernel: (F, 1, 9) float32
// out:    (F, B, 1, L) float32, row (f,b) at (f*B + b)*L
//
// One thread -> one float4 of outputs, ONE coalesced float4 load per thread.
// Halo quads (x[p-4..p-1], x[p+4..p+7]) come from neighbor lanes via
// shfl.up/shfl.down. Warp-edge lanes (0, 31) fetch their halo with a
// predicated extra global load (zero at row boundaries).
// L1 wavefronts per warp per 512B in+out: 4 LDG + 4 STG (+eps) vs 16 before.

#define Lc 131072
#define Fc 64
#define Bc 8
#define QUADS_PER_ROW (Lc / 4)            // 32768 = 2^15

__global__ __launch_bounds__(256) void dwconv1d_kernel(
    const float* __restrict__ x,
    const float* __restrict__ w,
    float* __restrict__ out)
{
    const unsigned FULL = 0xFFFFFFFFu;
    int t = blockIdx.x * blockDim.x + threadIdx.x;
    int q   = t & (QUADS_PER_ROW - 1);    // quad index within row
    int row = t >> 15;                    // b*F + f  (warp never straddles a row)
    int f = row & (Fc - 1);
    int b = row >> 6;
    int p = q << 2;                       // element offset within row
    int lane = threadIdx.x & 31;

    const float* xr = x + (size_t)row * Lc;

    // 9 warp-uniform weight loads (whole block shares f)
    const float* wf = w + f * 9;
    float k0 = wf[0], k1 = wf[1], k2 = wf[2], k3 = wf[3], k4 = wf[4],
          k5 = wf[5], k6 = wf[6], k7 = wf[7], k8 = wf[8];

    // Own quad: fully coalesced (lanes adjacent -> 4 lines / warp instr)
    float4 c = *reinterpret_cast<const float4*>(xr + p);

    // Warp-edge halo: only lanes 0 and 31 load (predicated; zero at row ends)
    float4 e = make_float4(0.f, 0.f, 0.f, 0.f);
    if (lane == 0) {
        if (p >= 4) e = *reinterpret_cast<const float4*>(xr + p - 4);
    } else if (lane == 31) {
        if (p + 4 < Lc) e = *reinterpret_cast<const float4*>(xr + p + 4);
    }

    // Interior halo via register exchange
    float4 m, n;
    m.x = __shfl_up_sync(FULL, c.x, 1);
    m.y = __shfl_up_sync(FULL, c.y, 1);
    m.z = __shfl_up_sync(FULL, c.z, 1);
    m.w = __shfl_up_sync(FULL, c.w, 1);
    n.x = __shfl_down_sync(FULL, c.x, 1);
    n.y = __shfl_down_sync(FULL, c.y, 1);
    n.z = __shfl_down_sync(FULL, c.z, 1);
    n.w = __shfl_down_sync(FULL, c.w, 1);
    if (lane == 0)  m = e;
    if (lane == 31) n = e;

    // a[i] = x[p - 4 + i], i = 0..11
    float a0 = m.x, a1 = m.y, a2  = m.z, a3  = m.w;
    float a4 = c.x, a5 = c.y, a6  = c.z, a7  = c.w;
    float a8 = n.x, a9 = n.y, a10 = n.z, a11 = n.w;

    float4 o;
    o.x = a0*k0 + a1*k1 + a2*k2 + a3*k3 + a4*k4 + a5*k5 + a6*k6 + a7*k7 + a8*k8;
    o.y = a1*k0 + a2*k1 + a3*k2 + a4*k3 + a5*k4 + a6*k5 + a7*k6 + a8*k7 + a9*k8;
    o.z = a2*k0 + a3*k1 + a4*k2 + a5*k3 + a6*k4 + a7*k5 + a8*k6 + a9*k7 + a10*k8;
    o.w = a3*k0 + a4*k1 + a5*k2 + a6*k3 + a7*k4 + a8*k5 + a9*k6 + a10*k7 + a11*k8;

    *reinterpret_cast<float4*>(out + ((size_t)(f * Bc + b)) * Lc + p) = o;
}

extern "C" void kernel_launch(void* const* d_in, const int* in_sizes, int n_in,
                              void* d_out, int out_size)
{
    const float* x = (const float*)d_in[0];
    const float* w = (const float*)d_in[1];
    float* out = (float*)d_out;

    // total quads = B*F*L/4 = 16,777,216 ; 256 threads/block -> 65536 blocks
    dim3 grid((Bc * Fc * QUADS_PER_ROW) / 256);
    dwconv1d_kernel<<<grid, 256>>>(x, w, out);
}

// round 7
// speedup vs baseline: 1.2676x; 1.0926x over previous
#include <cuda_runtime.h>

// Depthwise 1D conv: B=8, F=64, L=131072, K=9, pad=4 (SAME).
// x:      (B, F, L) float32, row (b,f) at (b*F + f)*L
// kernel: (F, 1, 9) float32
// out:    (F, B, 1, L) float32, row (f,b) at (f*B + b)*L
//
// 2 warp-strided quads per thread (quad q0 = base + lane, q1 = q0 + 32):
// every LDG/STG stays lane-adjacent (4-5 lines/warp instr). Halo via
// shfl.up/down; lanes 0/31 fetch warp-edge halo with predicated loads.
// __ldcs/__stcs: both streams touched once -> evict-first, no L2 thrash.

#define Lc 131072
#define Fc 64
#define Bc 8
#define QUADS_PER_ROW (Lc / 4)            // 32768 = 2^15
#define QPT 2                             // quads per thread

__global__ __launch_bounds__(256) void dwconv1d_kernel(
    const float* __restrict__ x,
    const float* __restrict__ w,
    float* __restrict__ out)
{
    const unsigned FULL = 0xFFFFFFFFu;
    int lane = threadIdx.x & 31;
    int warp = threadIdx.x >> 5;

    // Block covers 512 contiguous quads, all within one row (32768 % 512 == 0)
    int qblock = blockIdx.x * (256 * QPT);
    int row = qblock >> 15;               // b*F + f
    int f = row & (Fc - 1);
    int b = row >> 6;

    const float* xr = x + (size_t)row * Lc;
    float* orow = out + ((size_t)(f * Bc + b)) * Lc;

    // 9 warp-uniform weight loads (whole block shares f)
    const float* wf = w + f * 9;
    float k0 = wf[0], k1 = wf[1], k2 = wf[2], k3 = wf[3], k4 = wf[4],
          k5 = wf[5], k6 = wf[6], k7 = wf[7], k8 = wf[8];

    int qbase = (qblock & (QUADS_PER_ROW - 1)) + warp * (32 * QPT) + lane;

    // ---- Phase 1: issue ALL loads first (max MLP) ----
    float4 c[QPT];
    float4 e[QPT];
#pragma unroll
    for (int j = 0; j < QPT; j++) {
        int p = (qbase + j * 32) << 2;
        c[j] = __ldcs(reinterpret_cast<const float4*>(xr + p));
        e[j] = make_float4(0.f, 0.f, 0.f, 0.f);
        if (lane == 0) {
            if (p >= 4) e[j] = __ldcs(reinterpret_cast<const float4*>(xr + p - 4));
        } else if (lane == 31) {
            if (p + 4 < Lc) e[j] = __ldcs(reinterpret_cast<const float4*>(xr + p + 4));
        }
    }

    // ---- Phase 2: per-quad halo exchange + FMA tree + store ----
#pragma unroll
    for (int j = 0; j < QPT; j++) {
        int p = (qbase + j * 32) << 2;
        float4 m, n;
        m.x = __shfl_up_sync(FULL, c[j].x, 1);
        m.y = __shfl_up_sync(FULL, c[j].y, 1);
        m.z = __shfl_up_sync(FULL, c[j].z, 1);
        m.w = __shfl_up_sync(FULL, c[j].w, 1);
        n.x = __shfl_down_sync(FULL, c[j].x, 1);
        n.y = __shfl_down_sync(FULL, c[j].y, 1);
        n.z = __shfl_down_sync(FULL, c[j].z, 1);
        n.w = __shfl_down_sync(FULL, c[j].w, 1);
        if (lane == 0)  m = e[j];
        if (lane == 31) n = e[j];

        float a0 = m.x,    a1 = m.y,    a2  = m.z,    a3  = m.w;
        float a4 = c[j].x, a5 = c[j].y, a6  = c[j].z, a7  = c[j].w;
        float a8 = n.x,    a9 = n.y,    a10 = n.z,    a11 = n.w;

        float4 o;
        o.x = a0*k0 + a1*k1 + a2*k2 + a3*k3 + a4*k4 + a5*k5 + a6*k6 + a7*k7 + a8*k8;
        o.y = a1*k0 + a2*k1 + a3*k2 + a4*k3 + a5*k4 + a6*k5 + a7*k6 + a8*k7 + a9*k8;
        o.z = a2*k0 + a3*k1 + a4*k2 + a5*k3 + a6*k4 + a7*k5 + a8*k6 + a9*k7 + a10*k8;
        o.w = a3*k0 + a4*k1 + a5*k2 + a6*k3 + a7*k4 + a8*k5 + a9*k6 + a10*k7 + a11*k8;

        __stcs(reinterpret_cast<float4*>(orow + p), o);
    }
}

extern "C" void kernel_launch(void* const* d_in, const int* in_sizes, int n_in,
                              void* d_out, int out_size)
{
    const float* x = (const float*)d_in[0];
    const float* w = (const float*)d_in[1];
    float* out = (float*)d_out;

    // total quads = 16,777,216 ; 512 quads per block -> 32768 blocks
    dim3 grid((Bc * Fc * QUADS_PER_ROW) / (256 * QPT));
    dwconv1d_kernel<<<grid, 256>>>(x, w, out);
}

// round 8
// speedup vs baseline: 1.2820x; 1.0113x over previous
#include <cuda_runtime.h>

// Depthwise 1D conv: B=8, F=64, L=131072, K=9, pad=4 (SAME).
// x:      (B, F, L) float32, row (b,f) at (b*F + f)*L
// kernel: (F, 1, 9) float32
// out:    (F, B, 1, L) float32, row (f,b) at (f*B + b)*L
//
// 4 warp-strided quads per thread (quad qj = base + lane + j*32):
// every LDG/STG stays lane-adjacent (fully coalesced). Halo via
// shfl.up/down; lanes 0/31 fetch warp-edge halo with predicated loads.
// All loads front-batched (MLP~4-6 per thread). __ldcs/__stcs: streams
// touched once -> evict-first, no L2 thrash.

#define Lc 131072
#define Fc 64
#define Bc 8
#define QUADS_PER_ROW (Lc / 4)            // 32768 = 2^15
#define QPT 4                             // quads per thread

__global__ __launch_bounds__(256) void dwconv1d_kernel(
    const float* __restrict__ x,
    const float* __restrict__ w,
    float* __restrict__ out)
{
    const unsigned FULL = 0xFFFFFFFFu;
    int lane = threadIdx.x & 31;
    int warp = threadIdx.x >> 5;

    // Block covers 1024 contiguous quads, all within one row (32768 % 1024 == 0)
    int qblock = blockIdx.x * (256 * QPT);
    int row = qblock >> 15;               // b*F + f
    int f = row & (Fc - 1);
    int b = row >> 6;

    const float* xr = x + (size_t)row * Lc;
    float* orow = out + ((size_t)(f * Bc + b)) * Lc;

    // 9 warp-uniform weight loads (whole block shares f)
    const float* wf = w + f * 9;
    float k0 = wf[0], k1 = wf[1], k2 = wf[2], k3 = wf[3], k4 = wf[4],
          k5 = wf[5], k6 = wf[6], k7 = wf[7], k8 = wf[8];

    int qbase = (qblock & (QUADS_PER_ROW - 1)) + warp * (32 * QPT) + lane;

    // ---- Phase 1: issue ALL loads first (max MLP) ----
    float4 c[QPT];
    float4 e[QPT];
#pragma unroll
    for (int j = 0; j < QPT; j++) {
        int p = (qbase + j * 32) << 2;
        c[j] = __ldcs(reinterpret_cast<const float4*>(xr + p));
    }
#pragma unroll
    for (int j = 0; j < QPT; j++) {
        int p = (qbase + j * 32) << 2;
        e[j] = make_float4(0.f, 0.f, 0.f, 0.f);
        if (lane == 0) {
            if (p >= 4) e[j] = __ldcs(reinterpret_cast<const float4*>(xr + p - 4));
        } else if (lane == 31) {
            if (p + 4 < Lc) e[j] = __ldcs(reinterpret_cast<const float4*>(xr + p + 4));
        }
    }

    // ---- Phase 2: per-quad halo exchange + FMA tree + store ----
#pragma unroll
    for (int j = 0; j < QPT; j++) {
        int p = (qbase + j * 32) << 2;
        float4 m, n;
        m.x = __shfl_up_sync(FULL, c[j].x, 1);
        m.y = __shfl_up_sync(FULL, c[j].y, 1);
        m.z = __shfl_up_sync(FULL, c[j].z, 1);
        m.w = __shfl_up_sync(FULL, c[j].w, 1);
        n.x = __shfl_down_sync(FULL, c[j].x, 1);
        n.y = __shfl_down_sync(FULL, c[j].y, 1);
        n.z = __shfl_down_sync(FULL, c[j].z, 1);
        n.w = __shfl_down_sync(FULL, c[j].w, 1);
        if (lane == 0)  m = e[j];
        if (lane == 31) n = e[j];

        float a0 = m.x,    a1 = m.y,    a2  = m.z,    a3  = m.w;
        float a4 = c[j].x, a5 = c[j].y, a6  = c[j].z, a7  = c[j].w;
        float a8 = n.x,    a9 = n.y,    a10 = n.z,    a11 = n.w;

        float4 o;
        o.x = a0*k0 + a1*k1 + a2*k2 + a3*k3 + a4*k4 + a5*k5 + a6*k6 + a7*k7 + a8*k8;
        o.y = a1*k0 + a2*k1 + a3*k2 + a4*k3 + a5*k4 + a6*k5 + a7*k6 + a8*k7 + a9*k8;
        o.z = a2*k0 + a3*k1 + a4*k2 + a5*k3 + a6*k4 + a7*k5 + a8*k6 + a9*k7 + a10*k8;
        o.w = a3*k0 + a4*k1 + a5*k2 + a6*k3 + a7*k4 + a8*k5 + a9*k6 + a10*k7 + a11*k8;

        __stcs(reinterpret_cast<float4*>(orow + p), o);
    }
}

extern "C" void kernel_launch(void* const* d_in, const int* in_sizes, int n_in,
                              void* d_out, int out_size)
{
    const float* x = (const float*)d_in[0];
    const float* w = (const float*)d_in[1];
    float* out = (float*)d_out;

    // total quads = 16,777,216 ; 1024 quads per block -> 16384 blocks
    dim3 grid((Bc * Fc * QUADS_PER_ROW) / (256 * QPT));
    dwconv1d_kernel<<<grid, 256>>>(x, w, out);
}

// round 10
// speedup vs baseline: 1.2835x; 1.0012x over previous
#include <cuda_runtime.h>

// Depthwise 1D conv: B=8, F=64, L=131072, K=9, pad=4 (SAME).
// x:      (B, F, L) float32, row (b,f) at (b*F + f)*L
// kernel: (F, 1, 9) float32
// out:    (F, B, 1, L) float32, row (f,b) at (f*B + b)*L
//
// 4 warp-strided quads per thread (quad = Wbase + j*32 + lane): all LDG/STG
// lane-adjacent (fully coalesced). Halo entirely via indexed shuffles:
// lane 0's prev quad for chunk j IS lane 31's c[j-1]; lane 31's next quad
// IS lane 0's c[j+1]. Only 2 true edge loads per warp (warp-first prev,
// warp-last next), zeroed at row boundaries. __ldcs/__stcs: streamed once.

#define Lc 131072
#define Fc 64
#define Bc 8
#define QUADS_PER_ROW (Lc / 4)            // 32768 = 2^15
#define QPT 4                             // quads per thread

__global__ __launch_bounds__(256) void dwconv1d_kernel(
    const float* __restrict__ x,
    const float* __restrict__ w,
    float* __restrict__ out)
{
    const unsigned FULL = 0xFFFFFFFFu;
    int lane = threadIdx.x & 31;
    int warp = threadIdx.x >> 5;

    // Block covers 1024 contiguous quads, all within one row (32768 % 1024 == 0)
    int qblock = blockIdx.x * (256 * QPT);
    int row = qblock >> 15;               // b*F + f
    int f = row & (Fc - 1);
    int b = row >> 6;

    const float* xr = x + (size_t)row * Lc;
    float* orow = out + ((size_t)(f * Bc + b)) * Lc;

    // 9 warp-uniform weight loads (whole block shares f)
    const float* wf = w + f * 9;
    float k0 = wf[0], k1 = wf[1], k2 = wf[2], k3 = wf[3], k4 = wf[4],
          k5 = wf[5], k6 = wf[6], k7 = wf[7], k8 = wf[8];

    // Warp's within-row quad base (warp spans quads [qw, qw+128))
    int qw = (qblock & (QUADS_PER_ROW - 1)) + warp * (32 * QPT);

    // ---- Phase 1: issue ALL loads first (max MLP) ----
    // Edge quads: only one lane's value is ever read through the shuffle wrap.
    float4 eprev = make_float4(0.f, 0.f, 0.f, 0.f);  // quad qw-1 (lane 31)
    float4 enext = make_float4(0.f, 0.f, 0.f, 0.f);  // quad qw+128 (lane 0)
    if (lane == 31 && qw != 0)
        eprev = __ldcs(reinterpret_cast<const float4*>(xr + (qw << 2) - 4));
    if (lane == 0 && qw + 32 * QPT != QUADS_PER_ROW)
        enext = __ldcs(reinterpret_cast<const float4*>(xr + ((qw + 32 * QPT) << 2)));

    float4 c[QPT];
#pragma unroll
    for (int j = 0; j < QPT; j++)
        c[j] = __ldcs(reinterpret_cast<const float4*>(xr + ((qw + j * 32 + lane) << 2)));

    // ---- Phase 2: per-quad halo via indexed shuffle + FMA tree + store ----
    int up = (lane + 31) & 31;   // lane-1 mod 32
    int dn = (lane + 1) & 31;    // lane+1 mod 32
#pragma unroll
    for (int j = 0; j < QPT; j++) {
        // Source regs: wrap lanes carry the adjacent chunk's quad.
        float4 sm = c[j];        // read by lane l from lane l-1; lane 0 reads lane 31
        if (lane == 31) sm = (j == 0) ? eprev : c[j - 1];
        float4 sn = c[j];        // read by lane l from lane l+1; lane 31 reads lane 0
        if (lane == 0)  sn = (j == QPT - 1) ? enext : c[j + 1];

        float4 m, n;
        m.x = __shfl_sync(FULL, sm.x, up);
        m.y = __shfl_sync(FULL, sm.y, up);
        m.z = __shfl_sync(FULL, sm.z, up);
        m.w = __shfl_sync(FULL, sm.w, up);
        n.x = __shfl_sync(FULL, sn.x, dn);
        n.y = __shfl_sync(FULL, sn.y, dn);
        n.z = __shfl_sync(FULL, sn.z, dn);
        n.w = __shfl_sync(FULL, sn.w, dn);

        float a0 = m.x,    a1 = m.y,    a2  = m.z,    a3  = m.w;
        float a4 = c[j].x, a5 = c[j].y, a6  = c[j].z, a7  = c[j].w;
        float a8 = n.x,    a9 = n.y,    a10 = n.z,    a11 = n.w;

        float4 o;
        o.x = a0*k0 + a1*k1 + a2*k2 + a3*k3 + a4*k4 + a5*k5 + a6*k6 + a7*k7 + a8*k8;
        o.y = a1*k0 + a2*k1 + a3*k2 + a4*k3 + a5*k4 + a6*k5 + a7*k6 + a8*k7 + a9*k8;
        o.z = a2*k0 + a3*k1 + a4*k2 + a5*k3 + a6*k4 + a7*k5 + a8*k6 + a9*k7 + a10*k8;
        o.w = a3*k0 + a4*k1 + a5*k2 + a6*k3 + a7*k4 + a8*k5 + a9*k6 + a10*k7 + a11*k8;

        __stcs(reinterpret_cast<float4*>(orow + ((qw + j * 32 + lane) << 2)), o);
    }
}

extern "C" void kernel_launch(void* const* d_in, const int* in_sizes, int n_in,
                              void* d_out, int out_size)
{
    const float* x = (const float*)d_in[0];
    const float* w = (const float*)d_in[1];
    float* out = (float*)d_out;

    // total quads = 16,777,216 ; 1024 quads per block -> 16384 blocks
    dim3 grid((Bc * Fc * QUADS_PER_ROW) / (256 * QPT));
    dwconv1d_kernel<<<grid, 256>>>(x, w, out);
}